// round 11
// baseline (speedup 1.0000x reference)
#include <cuda_runtime.h>
#include <math.h>
#include <cstdint>

#define BB 4
#define SS 2048
#define EE 768
#define HH 12
#define DD 64
#define GK 768

// Scratch (static device globals: no allocation allowed)
// g_q/g_k/g_v/g_y hold tf32-rounded bit patterns (still valid floats).
__device__ float g_q[(size_t)BB * HH * SS * DD];
__device__ float g_k[(size_t)BB * HH * SS * DD];
__device__ float g_v[(size_t)BB * HH * SS * DD];
__device__ float g_y[(size_t)BB * SS * EE];
__device__ uint32_t g_xt[(size_t)BB * SS * EE];    // x -> tf32 bits
__device__ uint32_t g_wat[(size_t)EE * 3 * EE];    // W_attn -> tf32 bits
__device__ uint32_t g_wpt[(size_t)EE * EE];        // W_proj -> tf32 bits

// ======================= helpers ============================================
__device__ __forceinline__ uint32_t smem_u32(const void* p) {
    uint32_t a;
    asm("{ .reg .u64 t; cvta.to.shared.u64 t, %1; cvt.u32.u64 %0, t; }" : "=r"(a) : "l"(p));
    return a;
}
__device__ __forceinline__ void cp16(uint32_t dst, const void* src) {
    asm volatile("cp.async.cg.shared.global [%0], [%1], 16;" :: "r"(dst), "l"(src) : "memory");
}
__device__ __forceinline__ void cp_commit() {
    asm volatile("cp.async.commit_group;" ::: "memory");
}
template <int N>
__device__ __forceinline__ void cp_wait() {
    asm volatile("cp.async.wait_group %0;" :: "n"(N) : "memory");
}
__device__ __forceinline__ uint32_t f2tf32(float x) {
    uint32_t u;
    asm("cvt.rna.tf32.f32 %0, %1;" : "=r"(u) : "f"(x));
    return u;
}
__device__ __forceinline__ void mma_tf32(float* d, uint32_t a0, uint32_t a1, uint32_t a2,
                                         uint32_t a3, uint32_t b0, uint32_t b1) {
    asm volatile(
        "mma.sync.aligned.m16n8k8.row.col.f32.tf32.tf32.f32 "
        "{%0,%1,%2,%3}, {%4,%5,%6,%7}, {%8,%9}, {%0,%1,%2,%3};"
        : "+f"(d[0]), "+f"(d[1]), "+f"(d[2]), "+f"(d[3])
        : "r"(a0), "r"(a1), "r"(a2), "r"(a3), "r"(b0), "r"(b1));
}

// Fast exp2 on FMA pipe
__device__ __forceinline__ float fexp2(float x) {
    x = fmaxf(x, -126.f);
    float z = x + 12582912.f;
    int n = __float_as_int(z) - 0x4B400000;
    float fi = z - 12582912.f;
    float f = x - fi;
    float r = 1.3333558146e-3f;
    r = fmaf(r, f, 9.6181291e-3f);
    r = fmaf(r, f, 5.5504108664e-2f);
    r = fmaf(r, f, 2.4022650695910e-1f);
    r = fmaf(r, f, 6.9314718055995e-1f);
    r = fmaf(r, f, 1.0f);
    return r * __int_as_float((n + 127) << 23);
}

// ======================= fp32 -> tf32 bit pre-pass ==========================
__global__ void cvt_tf32_kernel(const float4* __restrict__ src, uint4* __restrict__ dst,
                                int n4) {
    int i = blockIdx.x * blockDim.x + threadIdx.x;
    if (i < n4) {
        float4 v = src[i];
        dst[i] = make_uint4(f2tf32(v.x), f2tf32(v.y), f2tf32(v.z), f2tf32(v.w));
    }
}

// ======================= tf32 mma.sync GEMM (unchanged, proven) =============
#define ABUF 18432            // 128*36*4
#define BBUF 17408            // 32*136*4
#define STAGE (ABUF + BBUF)   // 35840
#define GEMM_SMEM (2 * STAGE) // 71680

template <int MODE>
__global__ __launch_bounds__(256) void gemm_mma(const uint32_t* __restrict__ A_,
                                                const uint32_t* __restrict__ W,
                                                const float* __restrict__ bias,
                                                float* __restrict__ C, int N) {
    extern __shared__ char sm[];
    const uint32_t sbase = smem_u32(sm);

    const uint32_t* A = (MODE == 2) ? (const uint32_t*)g_y : A_;
    const int tid = threadIdx.x;
    const int wid = tid >> 5;
    const int lane = tid & 31;
    const int g = lane >> 2;
    const int t = lane & 3;
    const int bm = blockIdx.y * 128;
    const int bn = blockIdx.x * 128;
    const int wm = (wid >> 2) * 64;
    const int wn = (wid & 3) * 32;

    float acc[4][4][4];
#pragma unroll
    for (int mi = 0; mi < 4; mi++)
#pragma unroll
        for (int ni = 0; ni < 4; ni++)
#pragma unroll
            for (int r = 0; r < 4; r++) acc[mi][ni][r] = 0.f;

    const int am = tid >> 3;
    const int ac16 = (tid & 7) << 4;
    const int bk = tid >> 5;
    const int bn16 = (tid & 31) << 4;

#define ISSUE(s, buf)                                                                   \
    {                                                                                   \
        const int k0_ = (s) * 32;                                                       \
        const uint32_t sa_ = sbase + (buf) * STAGE;                                     \
        const uint32_t sb_ = sa_ + ABUF;                                                \
        _Pragma("unroll") for (int it = 0; it < 4; ++it) {                              \
            const int m_ = am + it * 32;                                                \
            cp16(sa_ + m_ * 144 + ac16, &A[(size_t)(bm + m_) * GK + k0_ + (ac16 >> 2)]);\
            const int k_ = bk + it * 8;                                                 \
            cp16(sb_ + k_ * 544 + bn16, &W[(size_t)(k0_ + k_) * N + bn + (bn16 >> 2)]); \
        }                                                                               \
        cp_commit();                                                                    \
    }

    ISSUE(0, 0);
    ISSUE(1, 1);

    for (int s = 0; s < 24; ++s) {
        const int buf = s & 1;
        if (s == 23) cp_wait<0>(); else cp_wait<1>();
        __syncthreads();

        const uint32_t* Af = (const uint32_t*)(sm + buf * STAGE);
        const uint32_t* Bf = (const uint32_t*)(sm + buf * STAGE + ABUF);

#pragma unroll
        for (int ks = 0; ks < 4; ++ks) {
            const int kk = ks * 8 + t;
            uint32_t b0[4], b1[4];
#pragma unroll
            for (int ni = 0; ni < 4; ++ni) {
                b0[ni] = Bf[kk * 136 + wn + ni * 8 + g];
                b1[ni] = Bf[(kk + 4) * 136 + wn + ni * 8 + g];
            }
#pragma unroll
            for (int mi = 0; mi < 4; ++mi) {
                const int r = wm + mi * 16 + g;
                uint32_t a0 = Af[r * 36 + kk];
                uint32_t a1 = Af[(r + 8) * 36 + kk];
                uint32_t a2 = Af[r * 36 + kk + 4];
                uint32_t a3 = Af[(r + 8) * 36 + kk + 4];
#pragma unroll
                for (int ni = 0; ni < 4; ++ni)
                    mma_tf32(acc[mi][ni], a0, a1, a2, a3, b0[ni], b1[ni]);
            }
        }
        __syncthreads();
        if (s + 2 < 24) ISSUE(s + 2, buf);
    }

#pragma unroll
    for (int mi = 0; mi < 4; ++mi) {
#pragma unroll
        for (int ni = 0; ni < 4; ++ni) {
            const int r0 = bm + wm + mi * 16 + g;
            const int c0 = bn + wn + ni * 8 + 2 * t;
            const float bz0 = __ldg(&bias[c0]);
            const float bz1 = __ldg(&bias[c0 + 1]);
            if (MODE == 1) {
                float2 v0 = make_float2(
                    __uint_as_float(f2tf32(acc[mi][ni][0] + bz0)),
                    __uint_as_float(f2tf32(acc[mi][ni][1] + bz1)));
                float2 v1 = make_float2(
                    __uint_as_float(f2tf32(acc[mi][ni][2] + bz0)),
                    __uint_as_float(f2tf32(acc[mi][ni][3] + bz1)));
                const int sec = c0 / EE;
                const int e = c0 - sec * EE;
                const int h = e >> 6, d = e & 63;
                float* dst = (sec == 0) ? g_q : ((sec == 1) ? g_k : g_v);
                {
                    const int b = r0 >> 11, srow = r0 & 2047;
                    *(float2*)&dst[(((size_t)b * HH + h) * SS + srow) * DD + d] = v0;
                }
                {
                    const int r1 = r0 + 8;
                    const int b = r1 >> 11, srow = r1 & 2047;
                    *(float2*)&dst[(((size_t)b * HH + h) * SS + srow) * DD + d] = v1;
                }
            } else {
                float2 v0 = make_float2(acc[mi][ni][0] + bz0, acc[mi][ni][1] + bz1);
                float2 v1 = make_float2(acc[mi][ni][2] + bz0, acc[mi][ni][3] + bz1);
                *(float2*)&C[(size_t)r0 * N + c0] = v0;
                *(float2*)&C[(size_t)(r0 + 8) * N + c0] = v1;
            }
        }
    }
}

// ======================= Flash attention via tf32 mma.sync ==================
// q-tile 128, k-tile 32, 256 threads / 8 warps; warp w owns q rows [16w,16w+16).
// K/V/mask loaded straight via cp.async, DOUBLE-BUFFERED: load(kt+1) overlaps
// compute(kt). K read directly as B-fragment from Ks[key][d] stride 68
// (bank 4g+t, conflict-free) -> no transpose store. V stride 72 (bank 8t+g).
#define AQ_STR 68
#define KS_STR 68
#define VS_STR 72
#define KTILE 32
#define TBUF (KTILE * KS_STR + KTILE * VS_STR + KTILE)  // 2176+2304+32 = 4512 floats
#define ATTN_SMEM_FLOATS (128 * AQ_STR + 2 * TBUF)      // 8704 + 9024 = 17728
#define ATTN_SMEM_BYTES (ATTN_SMEM_FLOATS * 4)          // 70912 B -> 2 CTAs/SM

__global__ __launch_bounds__(256, 2) void attn_mma(const int* __restrict__ att_mask) {
    extern __shared__ float smf[];
    float* Qs = smf;  // [q][d] stride 68
    const uint32_t sbase = smem_u32(smf);

    const int qt = (int)gridDim.x - 1 - (int)blockIdx.x;
    const int bh = blockIdx.y;
    const int b = bh / HH;
    const int h = bh % HH;
    const int tid = threadIdx.x;
    const int wid = tid >> 5;
    const int lane = tid & 31;
    const int g = lane >> 2;
    const int t = lane & 3;
    const int q0 = qt * 128;

    const float* qptr = g_q + (size_t)bh * SS * DD;
    const float* kptr = g_k + (size_t)bh * SS * DD;
    const float* vptr = g_v + (size_t)bh * SS * DD;

    // Load Q tile [128][64] row-major (visible after first __syncthreads)
#pragma unroll
    for (int it = 0; it < 8; it++) {
        int j = tid + it * 256;
        int q = j >> 4;
        int c4 = (j & 15) << 2;
        *(float4*)&Qs[q * AQ_STR + c4] = *(const float4*)&qptr[(size_t)(q0 + q) * 64 + c4];
    }

    // cp.async K/V/mask tile loader: 32 keys x 64 floats each = 512 chunks of 16B
#define AISSUE(kt_, buf_)                                                               \
    {                                                                                   \
        const uint32_t ks_ = sbase + (128 * AQ_STR + (buf_) * TBUF) * 4;                \
        const uint32_t vs_ = ks_ + KTILE * KS_STR * 4;                                  \
        const uint32_t ms_ = vs_ + KTILE * VS_STR * 4;                                  \
        _Pragma("unroll") for (int it = 0; it < 2; ++it) {                              \
            const int c_ = tid + it * 256;                                              \
            const int row_ = c_ >> 4;                                                   \
            const int cb_ = (c_ & 15) << 4;                                             \
            cp16(ks_ + row_ * (KS_STR * 4) + cb_,                                       \
                 &kptr[(size_t)((kt_) * KTILE + row_) * 64 + (cb_ >> 2)]);              \
            cp16(vs_ + row_ * (VS_STR * 4) + cb_,                                       \
                 &vptr[(size_t)((kt_) * KTILE + row_) * 64 + (cb_ >> 2)]);              \
        }                                                                               \
        if (tid < 8) cp16(ms_ + tid * 16, &att_mask[b * SS + (kt_) * KTILE + tid * 4]); \
        cp_commit();                                                                    \
    }

    float ofrag[8][4];
#pragma unroll
    for (int nd = 0; nd < 8; nd++)
#pragma unroll
        for (int r = 0; r < 4; r++) ofrag[nd][r] = 0.f;
    float m0 = -1e30f, m1 = -1e30f, l0 = 0.f, l1 = 0.f;

    const float SC = 0.125f * 1.4426950408889634f;
    const int rowl = wid * 16 + g;
    const int qg0 = q0 + rowl, qg1 = qg0 + 8;
    const int bl = lane & ~3;
    const int ktmax = 4 * qt + 3;  // keys up to q0+127

    AISSUE(0, 0);

    for (int kt = 0; kt <= ktmax; kt++) {
        const int buf = kt & 1;
        cp_wait<0>();
        __syncthreads();
        if (kt < ktmax) AISSUE(kt + 1, buf ^ 1);

        const float* Ks = smf + 128 * AQ_STR + buf * TBUF;
        const float* Vs = Ks + KTILE * KS_STR;
        const int* msk = (const int*)(Vs + KTILE * VS_STR);

        // ---- scores: 4 ni frags over 32 keys ----
        float sf[4][4];
#pragma unroll
        for (int ni = 0; ni < 4; ni++)
#pragma unroll
            for (int r = 0; r < 4; r++) sf[ni][r] = 0.f;
#pragma unroll
        for (int dk = 0; dk < 8; dk++) {
            const int k0 = dk * 8;
            uint32_t a0 = __float_as_uint(Qs[rowl * AQ_STR + k0 + t]);
            uint32_t a1 = __float_as_uint(Qs[(rowl + 8) * AQ_STR + k0 + t]);
            uint32_t a2 = __float_as_uint(Qs[rowl * AQ_STR + k0 + t + 4]);
            uint32_t a3 = __float_as_uint(Qs[(rowl + 8) * AQ_STR + k0 + t + 4]);
#pragma unroll
            for (int ni = 0; ni < 4; ni++) {
                uint32_t b0 = __float_as_uint(Ks[(ni * 8 + g) * KS_STR + k0 + t]);
                uint32_t b1 = __float_as_uint(Ks[(ni * 8 + g) * KS_STR + k0 + t + 4]);
                mma_tf32(sf[ni], a0, a1, a2, a3, b0, b1);
            }
        }

        // ---- softmax (log2 domain) ----
        const bool tileFull = (kt * KTILE + KTILE - 1) <= q0;
        float mx0 = -1e30f, mx1 = -1e30f;
#pragma unroll
        for (int ni = 0; ni < 4; ni++) {
            const int cl0 = ni * 8 + 2 * t;
            const int cg0 = kt * KTILE + cl0;
            const float tb0 = msk[cl0] ? 0.f : -1e30f;
            const float tb1 = msk[cl0 + 1] ? 0.f : -1e30f;
            float v00 = fmaf(sf[ni][0], SC, tb0);
            float v01 = fmaf(sf[ni][1], SC, tb1);
            float v10 = fmaf(sf[ni][2], SC, tb0);
            float v11 = fmaf(sf[ni][3], SC, tb1);
            if (!tileFull) {
                if (cg0 > qg0) v00 = -1e30f;
                if (cg0 + 1 > qg0) v01 = -1e30f;
                if (cg0 > qg1) v10 = -1e30f;
                if (cg0 + 1 > qg1) v11 = -1e30f;
            }
            sf[ni][0] = v00; sf[ni][1] = v01; sf[ni][2] = v10; sf[ni][3] = v11;
            mx0 = fmaxf(mx0, fmaxf(v00, v01));
            mx1 = fmaxf(mx1, fmaxf(v10, v11));
        }
        mx0 = fmaxf(mx0, __shfl_xor_sync(0xffffffffu, mx0, 1));
        mx0 = fmaxf(mx0, __shfl_xor_sync(0xffffffffu, mx0, 2));
        mx1 = fmaxf(mx1, __shfl_xor_sync(0xffffffffu, mx1, 1));
        mx1 = fmaxf(mx1, __shfl_xor_sync(0xffffffffu, mx1, 2));
        const float mn0 = fmaxf(m0, mx0), mn1 = fmaxf(m1, mx1);
        const float al0 = fexp2(m0 - mn0), al1 = fexp2(m1 - mn1);
        float s0 = 0.f, s1 = 0.f;
#pragma unroll
        for (int ni = 0; ni < 4; ni++) {
            sf[ni][0] = fexp2(sf[ni][0] - mn0);
            sf[ni][1] = fexp2(sf[ni][1] - mn0);
            sf[ni][2] = fexp2(sf[ni][2] - mn1);
            sf[ni][3] = fexp2(sf[ni][3] - mn1);
            s0 += sf[ni][0] + sf[ni][1];
            s1 += sf[ni][2] + sf[ni][3];
        }
        s0 += __shfl_xor_sync(0xffffffffu, s0, 1);
        s0 += __shfl_xor_sync(0xffffffffu, s0, 2);
        s1 += __shfl_xor_sync(0xffffffffu, s1, 1);
        s1 += __shfl_xor_sync(0xffffffffu, s1, 2);
        l0 = l0 * al0 + s0;
        l1 = l1 * al1 + s1;
        m0 = mn0;
        m1 = mn1;
#pragma unroll
        for (int nd = 0; nd < 8; nd++) {
            ofrag[nd][0] *= al0;
            ofrag[nd][1] *= al0;
            ofrag[nd][2] *= al1;
            ofrag[nd][3] *= al1;
        }

        // ---- PV: P acc-layout -> A-layout via shuffles, then mma over V ----
        const int src0 = bl + (t >> 1);
        const int src1 = src0 + 2;
        const bool odd = (t & 1);
#pragma unroll
        for (int kc = 0; kc < 4; kc++) {
            float q00 = __shfl_sync(0xffffffffu, sf[kc][0], src0);
            float q01 = __shfl_sync(0xffffffffu, sf[kc][1], src0);
            float q10 = __shfl_sync(0xffffffffu, sf[kc][2], src0);
            float q11 = __shfl_sync(0xffffffffu, sf[kc][3], src0);
            float r00 = __shfl_sync(0xffffffffu, sf[kc][0], src1);
            float r01 = __shfl_sync(0xffffffffu, sf[kc][1], src1);
            float r10 = __shfl_sync(0xffffffffu, sf[kc][2], src1);
            float r11 = __shfl_sync(0xffffffffu, sf[kc][3], src1);
            uint32_t pa0 = f2tf32(odd ? q01 : q00);
            uint32_t pa1 = f2tf32(odd ? q11 : q10);
            uint32_t pa2 = f2tf32(odd ? r01 : r00);
            uint32_t pa3 = f2tf32(odd ? r11 : r10);
            const int kb = kc * 8;
#pragma unroll
            for (int nd = 0; nd < 8; nd++) {
                uint32_t b0 = __float_as_uint(Vs[(kb + t) * VS_STR + nd * 8 + g]);
                uint32_t b1 = __float_as_uint(Vs[(kb + t + 4) * VS_STR + nd * 8 + g]);
                mma_tf32(ofrag[nd], pa0, pa1, pa2, pa3, b0, b1);
            }
        }
    }

    // ---- epilogue: write g_y pre-rounded to tf32 (gemm2's A operand) ----
    const float inv0 = 1.0f / l0, inv1 = 1.0f / l1;
    const int r0 = q0 + rowl, r1 = r0 + 8;
#pragma unroll
    for (int nd = 0; nd < 8; nd++) {
        const int c0 = nd * 8 + 2 * t;
        float2 v0 = make_float2(__uint_as_float(f2tf32(ofrag[nd][0] * inv0)),
                                __uint_as_float(f2tf32(ofrag[nd][1] * inv0)));
        float2 v1 = make_float2(__uint_as_float(f2tf32(ofrag[nd][2] * inv1)),
                                __uint_as_float(f2tf32(ofrag[nd][3] * inv1)));
        *(float2*)&g_y[((size_t)b * SS + r0) * EE + h * 64 + c0] = v0;
        *(float2*)&g_y[((size_t)b * SS + r1) * EE + h * 64 + c0] = v1;
    }
}

// ---------------------------------------------------------------------------
extern "C" void kernel_launch(void* const* d_in, const int* in_sizes, int n_in,
                              void* d_out, int out_size) {
    const float* x = nullptr;
    const float* W_attn = nullptr;
    const float* b_attn = nullptr;
    const float* W_proj = nullptr;
    const float* b_proj = nullptr;
    const int* att_mask = nullptr;
    for (int i = 0; i < n_in; i++) {
        switch (in_sizes[i]) {
            case BB * SS * EE:   x = (const float*)d_in[i]; break;
            case EE * 3 * EE:    W_attn = (const float*)d_in[i]; break;
            case 3 * EE:         b_attn = (const float*)d_in[i]; break;
            case EE * EE:        W_proj = (const float*)d_in[i]; break;
            case EE:             b_proj = (const float*)d_in[i]; break;
            case BB * SS:        att_mask = (const int*)d_in[i]; break;
            default: break;
        }
    }
    float* out = (float*)d_out;

    static bool attr_set = false;
    if (!attr_set) {
        cudaFuncSetAttribute(attn_mma, cudaFuncAttributeMaxDynamicSharedMemorySize,
                             ATTN_SMEM_BYTES);
        cudaFuncSetAttribute(gemm_mma<1>, cudaFuncAttributeMaxDynamicSharedMemorySize,
                             GEMM_SMEM);
        cudaFuncSetAttribute(gemm_mma<2>, cudaFuncAttributeMaxDynamicSharedMemorySize,
                             GEMM_SMEM);
        attr_set = true;
    }

    uint32_t *xt, *wat, *wpt;
    cudaGetSymbolAddress((void**)&xt, g_xt);
    cudaGetSymbolAddress((void**)&wat, g_wat);
    cudaGetSymbolAddress((void**)&wpt, g_wpt);

    // 0) Pre-convert inputs to tf32 bit arrays
    {
        int n4;
        n4 = BB * SS * EE / 4;
        cvt_tf32_kernel<<<(n4 + 255) / 256, 256>>>((const float4*)x, (uint4*)xt, n4);
        n4 = EE * 3 * EE / 4;
        cvt_tf32_kernel<<<(n4 + 255) / 256, 256>>>((const float4*)W_attn, (uint4*)wat, n4);
        n4 = EE * EE / 4;
        cvt_tf32_kernel<<<(n4 + 255) / 256, 256>>>((const float4*)W_proj, (uint4*)wpt, n4);
    }

    // 1) QKV GEMM (tf32 mma.sync) + tf32-rounded scatter
    gemm_mma<1><<<dim3(3 * EE / 128, BB * SS / 128), 256, GEMM_SMEM>>>(
        xt, wat, b_attn, nullptr, 3 * EE);

    // 2) Flash attention (tf32 mma.sync, cp.async double-buffered K/V)
    attn_mma<<<dim3(SS / 128, BB * HH), 256, ATTN_SMEM_BYTES>>>(att_mask);

    // 3) Projection GEMM (reads tf32-rounded g_y)
    gemm_mma<2><<<dim3(EE / 128, BB * SS / 128), 256, GEMM_SMEM>>>(
        nullptr, wpt, b_proj, out, EE);
}

// round 12
// speedup vs baseline: 1.3844x; 1.3844x over previous
#include <cuda_runtime.h>
#include <math.h>
#include <cstdint>

#define BB 4
#define SS 2048
#define EE 768
#define HH 12
#define DD 64
#define GK 768

// Scratch (static device globals: no allocation allowed)
// g_q/g_k/g_v/g_y hold tf32-rounded bit patterns (still valid floats).
__device__ float g_q[(size_t)BB * HH * SS * DD];
__device__ float g_k[(size_t)BB * HH * SS * DD];
__device__ float g_v[(size_t)BB * HH * SS * DD];
__device__ float g_y[(size_t)BB * SS * EE];
__device__ uint32_t g_xt[(size_t)BB * SS * EE];    // x -> tf32 bits
__device__ uint32_t g_wat[(size_t)EE * 3 * EE];    // W_attn -> tf32 bits
__device__ uint32_t g_wpt[(size_t)EE * EE];        // W_proj -> tf32 bits

// ======================= helpers ============================================
__device__ __forceinline__ uint32_t smem_u32(const void* p) {
    uint32_t a;
    asm("{ .reg .u64 t; cvta.to.shared.u64 t, %1; cvt.u32.u64 %0, t; }" : "=r"(a) : "l"(p));
    return a;
}
__device__ __forceinline__ void cp16(uint32_t dst, const void* src) {
    asm volatile("cp.async.cg.shared.global [%0], [%1], 16;" :: "r"(dst), "l"(src) : "memory");
}
__device__ __forceinline__ void cp_commit() {
    asm volatile("cp.async.commit_group;" ::: "memory");
}
template <int N>
__device__ __forceinline__ void cp_wait() {
    asm volatile("cp.async.wait_group %0;" :: "n"(N) : "memory");
}
__device__ __forceinline__ uint32_t f2tf32(float x) {
    uint32_t u;
    asm("cvt.rna.tf32.f32 %0, %1;" : "=r"(u) : "f"(x));
    return u;
}
__device__ __forceinline__ void mma_tf32(float* d, uint32_t a0, uint32_t a1, uint32_t a2,
                                         uint32_t a3, uint32_t b0, uint32_t b1) {
    asm volatile(
        "mma.sync.aligned.m16n8k8.row.col.f32.tf32.tf32.f32 "
        "{%0,%1,%2,%3}, {%4,%5,%6,%7}, {%8,%9}, {%0,%1,%2,%3};"
        : "+f"(d[0]), "+f"(d[1]), "+f"(d[2]), "+f"(d[3])
        : "r"(a0), "r"(a1), "r"(a2), "r"(a3), "r"(b0), "r"(b1));
}

// Fast exp2 on FMA pipe
__device__ __forceinline__ float fexp2(float x) {
    x = fmaxf(x, -126.f);
    float z = x + 12582912.f;
    int n = __float_as_int(z) - 0x4B400000;
    float fi = z - 12582912.f;
    float f = x - fi;
    float r = 1.3333558146e-3f;
    r = fmaf(r, f, 9.6181291e-3f);
    r = fmaf(r, f, 5.5504108664e-2f);
    r = fmaf(r, f, 2.4022650695910e-1f);
    r = fmaf(r, f, 6.9314718055995e-1f);
    r = fmaf(r, f, 1.0f);
    return r * __int_as_float((n + 127) << 23);
}

// ======================= fp32 -> tf32 bit pre-pass ==========================
__global__ void cvt_tf32_kernel(const float4* __restrict__ src, uint4* __restrict__ dst,
                                int n4) {
    int i = blockIdx.x * blockDim.x + threadIdx.x;
    if (i < n4) {
        float4 v = src[i];
        dst[i] = make_uint4(f2tf32(v.x), f2tf32(v.y), f2tf32(v.z), f2tf32(v.w));
    }
}

// ======================= tf32 mma.sync GEMM (unchanged, proven) =============
#define ABUF 18432            // 128*36*4
#define BBUF 17408            // 32*136*4
#define STAGE (ABUF + BBUF)   // 35840
#define GEMM_SMEM (2 * STAGE) // 71680

template <int MODE>
__global__ __launch_bounds__(256) void gemm_mma(const uint32_t* __restrict__ A_,
                                                const uint32_t* __restrict__ W,
                                                const float* __restrict__ bias,
                                                float* __restrict__ C, int N) {
    extern __shared__ char sm[];
    const uint32_t sbase = smem_u32(sm);

    const uint32_t* A = (MODE == 2) ? (const uint32_t*)g_y : A_;
    const int tid = threadIdx.x;
    const int wid = tid >> 5;
    const int lane = tid & 31;
    const int g = lane >> 2;
    const int t = lane & 3;
    const int bm = blockIdx.y * 128;
    const int bn = blockIdx.x * 128;
    const int wm = (wid >> 2) * 64;
    const int wn = (wid & 3) * 32;

    float acc[4][4][4];
#pragma unroll
    for (int mi = 0; mi < 4; mi++)
#pragma unroll
        for (int ni = 0; ni < 4; ni++)
#pragma unroll
            for (int r = 0; r < 4; r++) acc[mi][ni][r] = 0.f;

    const int am = tid >> 3;
    const int ac16 = (tid & 7) << 4;
    const int bk = tid >> 5;
    const int bn16 = (tid & 31) << 4;

#define ISSUE(s, buf)                                                                   \
    {                                                                                   \
        const int k0_ = (s) * 32;                                                       \
        const uint32_t sa_ = sbase + (buf) * STAGE;                                     \
        const uint32_t sb_ = sa_ + ABUF;                                                \
        _Pragma("unroll") for (int it = 0; it < 4; ++it) {                              \
            const int m_ = am + it * 32;                                                \
            cp16(sa_ + m_ * 144 + ac16, &A[(size_t)(bm + m_) * GK + k0_ + (ac16 >> 2)]);\
            const int k_ = bk + it * 8;                                                 \
            cp16(sb_ + k_ * 544 + bn16, &W[(size_t)(k0_ + k_) * N + bn + (bn16 >> 2)]); \
        }                                                                               \
        cp_commit();                                                                    \
    }

    ISSUE(0, 0);
    ISSUE(1, 1);

    for (int s = 0; s < 24; ++s) {
        const int buf = s & 1;
        if (s == 23) cp_wait<0>(); else cp_wait<1>();
        __syncthreads();

        const uint32_t* Af = (const uint32_t*)(sm + buf * STAGE);
        const uint32_t* Bf = (const uint32_t*)(sm + buf * STAGE + ABUF);

#pragma unroll
        for (int ks = 0; ks < 4; ++ks) {
            const int kk = ks * 8 + t;
            uint32_t b0[4], b1[4];
#pragma unroll
            for (int ni = 0; ni < 4; ++ni) {
                b0[ni] = Bf[kk * 136 + wn + ni * 8 + g];
                b1[ni] = Bf[(kk + 4) * 136 + wn + ni * 8 + g];
            }
#pragma unroll
            for (int mi = 0; mi < 4; ++mi) {
                const int r = wm + mi * 16 + g;
                uint32_t a0 = Af[r * 36 + kk];
                uint32_t a1 = Af[(r + 8) * 36 + kk];
                uint32_t a2 = Af[r * 36 + kk + 4];
                uint32_t a3 = Af[(r + 8) * 36 + kk + 4];
#pragma unroll
                for (int ni = 0; ni < 4; ++ni)
                    mma_tf32(acc[mi][ni], a0, a1, a2, a3, b0[ni], b1[ni]);
            }
        }
        __syncthreads();
        if (s + 2 < 24) ISSUE(s + 2, buf);
    }

#pragma unroll
    for (int mi = 0; mi < 4; ++mi) {
#pragma unroll
        for (int ni = 0; ni < 4; ++ni) {
            const int r0 = bm + wm + mi * 16 + g;
            const int c0 = bn + wn + ni * 8 + 2 * t;
            const float bz0 = __ldg(&bias[c0]);
            const float bz1 = __ldg(&bias[c0 + 1]);
            if (MODE == 1) {
                float2 v0 = make_float2(
                    __uint_as_float(f2tf32(acc[mi][ni][0] + bz0)),
                    __uint_as_float(f2tf32(acc[mi][ni][1] + bz1)));
                float2 v1 = make_float2(
                    __uint_as_float(f2tf32(acc[mi][ni][2] + bz0)),
                    __uint_as_float(f2tf32(acc[mi][ni][3] + bz1)));
                const int sec = c0 / EE;
                const int e = c0 - sec * EE;
                const int h = e >> 6, d = e & 63;
                float* dst = (sec == 0) ? g_q : ((sec == 1) ? g_k : g_v);
                {
                    const int b = r0 >> 11, srow = r0 & 2047;
                    *(float2*)&dst[(((size_t)b * HH + h) * SS + srow) * DD + d] = v0;
                }
                {
                    const int r1 = r0 + 8;
                    const int b = r1 >> 11, srow = r1 & 2047;
                    *(float2*)&dst[(((size_t)b * HH + h) * SS + srow) * DD + d] = v1;
                }
            } else {
                float2 v0 = make_float2(acc[mi][ni][0] + bz0, acc[mi][ni][1] + bz1);
                float2 v1 = make_float2(acc[mi][ni][2] + bz0, acc[mi][ni][3] + bz1);
                *(float2*)&C[(size_t)r0 * N + c0] = v0;
                *(float2*)&C[(size_t)(r0 + 8) * N + c0] = v1;
            }
        }
    }
}

// ======================= Flash attention via tf32 mma.sync ==================
// R9 structure; ONE change: Q fragments live in registers (loaded once from
// gmem), Qs smem tile removed. Kt/Vs/Ps layouts identical to R9.
#define KV_STR 72
#define ATTN_SMEM_FLOATS (64 * KV_STR + 64 * KV_STR + 64)
#define ATTN_SMEM_BYTES (ATTN_SMEM_FLOATS * 4)   // 37120 B

__global__ __launch_bounds__(256, 2) void attn_mma(const int* __restrict__ att_mask) {
    extern __shared__ float smf[];
    float* Kt = smf;                       // [d][key] stride 72
    float* Vs = Kt + 64 * KV_STR;          // [key][d] stride 72
    int* msk = (int*)(Vs + 64 * KV_STR);

    const int qt = (int)gridDim.x - 1 - (int)blockIdx.x;
    const int bh = blockIdx.y;
    const int b = bh / HH;
    const int h = bh % HH;
    const int tid = threadIdx.x;
    const int wid = tid >> 5;
    const int lane = tid & 31;
    const int g = lane >> 2;
    const int t = lane & 3;
    const int q0 = qt * 128;

    const float* qptr = g_q + (size_t)bh * SS * DD;
    const float* kptr = g_k + (size_t)bh * SS * DD;
    const float* vptr = g_v + (size_t)bh * SS * DD;

    const int rowl = wid * 16 + g;
    const int qg0 = q0 + rowl, qg1 = qg0 + 8;
    const int bl = lane & ~3;
    const int ktmax = 2 * qt + 1;

    // ---- Q fragments: loaded ONCE from gmem into registers ----
    uint32_t qf[8][4];
    {
        const float* qr0 = qptr + (size_t)(q0 + rowl) * 64;
        const float* qr1 = qr0 + 8 * 64;
#pragma unroll
        for (int dk = 0; dk < 8; dk++) {
            const int k0 = dk * 8;
            qf[dk][0] = __float_as_uint(__ldg(qr0 + k0 + t));
            qf[dk][1] = __float_as_uint(__ldg(qr1 + k0 + t));
            qf[dk][2] = __float_as_uint(__ldg(qr0 + k0 + t + 4));
            qf[dk][3] = __float_as_uint(__ldg(qr1 + k0 + t + 4));
        }
    }

    float ofrag[8][4];
#pragma unroll
    for (int nd = 0; nd < 8; nd++)
#pragma unroll
        for (int r = 0; r < 4; r++) ofrag[nd][r] = 0.f;
    float m0 = -1e30f, m1 = -1e30f, l0 = 0.f, l1 = 0.f;

    const float SC = 0.125f * 1.4426950408889634f;

    const int krow = (lane & 31) + (wid & 1) * 32;
    const int kc4 = ((wid >> 1) << 2);

    for (int kt = 0; kt <= ktmax; kt++) {
        __syncthreads();
#pragma unroll
        for (int it = 0; it < 4; it++) {
            const int c4 = kc4 + it * 16;
            float4 kv = *(const float4*)&kptr[(size_t)(kt * 64 + krow) * 64 + c4];
            Kt[(c4 + 0) * KV_STR + krow] = kv.x;
            Kt[(c4 + 1) * KV_STR + krow] = kv.y;
            Kt[(c4 + 2) * KV_STR + krow] = kv.z;
            Kt[(c4 + 3) * KV_STR + krow] = kv.w;
        }
#pragma unroll
        for (int it = 0; it < 4; it++) {
            int j = tid + it * 256;
            int r = j >> 4;
            int c4 = (j & 15) << 2;
            *(float4*)&Vs[r * KV_STR + c4] =
                *(const float4*)&vptr[(size_t)(kt * 64 + r) * 64 + c4];
        }
        if (tid < 64) msk[tid] = att_mask[b * SS + kt * 64 + tid];
        __syncthreads();

        // ---- scores ----
        float sf[8][4];
#pragma unroll
        for (int ni = 0; ni < 8; ni++)
#pragma unroll
            for (int r = 0; r < 4; r++) sf[ni][r] = 0.f;
#pragma unroll
        for (int dk = 0; dk < 8; dk++) {
            const int k0 = dk * 8;
#pragma unroll
            for (int ni = 0; ni < 8; ni++) {
                uint32_t b0 = __float_as_uint(Kt[(k0 + t) * KV_STR + ni * 8 + g]);
                uint32_t b1 = __float_as_uint(Kt[(k0 + t + 4) * KV_STR + ni * 8 + g]);
                mma_tf32(sf[ni], qf[dk][0], qf[dk][1], qf[dk][2], qf[dk][3], b0, b1);
            }
        }

        // ---- softmax (log2 domain) ----
        const bool tileFull = (kt * 64 + 63) <= q0;
        float mx0 = -1e30f, mx1 = -1e30f;
#pragma unroll
        for (int ni = 0; ni < 8; ni++) {
            const int cl0 = ni * 8 + 2 * t;
            const int cg0 = kt * 64 + cl0;
            const float tb0 = msk[cl0] ? 0.f : -1e30f;
            const float tb1 = msk[cl0 + 1] ? 0.f : -1e30f;
            float v00 = fmaf(sf[ni][0], SC, tb0);
            float v01 = fmaf(sf[ni][1], SC, tb1);
            float v10 = fmaf(sf[ni][2], SC, tb0);
            float v11 = fmaf(sf[ni][3], SC, tb1);
            if (!tileFull) {
                if (cg0 > qg0) v00 = -1e30f;
                if (cg0 + 1 > qg0) v01 = -1e30f;
                if (cg0 > qg1) v10 = -1e30f;
                if (cg0 + 1 > qg1) v11 = -1e30f;
            }
            sf[ni][0] = v00; sf[ni][1] = v01; sf[ni][2] = v10; sf[ni][3] = v11;
            mx0 = fmaxf(mx0, fmaxf(v00, v01));
            mx1 = fmaxf(mx1, fmaxf(v10, v11));
        }
        mx0 = fmaxf(mx0, __shfl_xor_sync(0xffffffffu, mx0, 1));
        mx0 = fmaxf(mx0, __shfl_xor_sync(0xffffffffu, mx0, 2));
        mx1 = fmaxf(mx1, __shfl_xor_sync(0xffffffffu, mx1, 1));
        mx1 = fmaxf(mx1, __shfl_xor_sync(0xffffffffu, mx1, 2));
        const float mn0 = fmaxf(m0, mx0), mn1 = fmaxf(m1, mx1);
        const float al0 = fexp2(m0 - mn0), al1 = fexp2(m1 - mn1);
        float s0 = 0.f, s1 = 0.f;
#pragma unroll
        for (int ni = 0; ni < 8; ni++) {
            sf[ni][0] = fexp2(sf[ni][0] - mn0);
            sf[ni][1] = fexp2(sf[ni][1] - mn0);
            sf[ni][2] = fexp2(sf[ni][2] - mn1);
            sf[ni][3] = fexp2(sf[ni][3] - mn1);
            s0 += sf[ni][0] + sf[ni][1];
            s1 += sf[ni][2] + sf[ni][3];
        }
        s0 += __shfl_xor_sync(0xffffffffu, s0, 1);
        s0 += __shfl_xor_sync(0xffffffffu, s0, 2);
        s1 += __shfl_xor_sync(0xffffffffu, s1, 1);
        s1 += __shfl_xor_sync(0xffffffffu, s1, 2);
        l0 = l0 * al0 + s0;
        l1 = l1 * al1 + s1;
        m0 = mn0;
        m1 = mn1;
#pragma unroll
        for (int nd = 0; nd < 8; nd++) {
            ofrag[nd][0] *= al0;
            ofrag[nd][1] *= al0;
            ofrag[nd][2] *= al1;
            ofrag[nd][3] *= al1;
        }

        // ---- PV ----
        const int src0 = bl + (t >> 1);
        const int src1 = src0 + 2;
        const bool odd = (t & 1);
#pragma unroll
        for (int kc = 0; kc < 8; kc++) {
            float q00 = __shfl_sync(0xffffffffu, sf[kc][0], src0);
            float q01 = __shfl_sync(0xffffffffu, sf[kc][1], src0);
            float q10 = __shfl_sync(0xffffffffu, sf[kc][2], src0);
            float q11 = __shfl_sync(0xffffffffu, sf[kc][3], src0);
            float r00 = __shfl_sync(0xffffffffu, sf[kc][0], src1);
            float r01 = __shfl_sync(0xffffffffu, sf[kc][1], src1);
            float r10 = __shfl_sync(0xffffffffu, sf[kc][2], src1);
            float r11 = __shfl_sync(0xffffffffu, sf[kc][3], src1);
            uint32_t pa0 = f2tf32(odd ? q01 : q00);
            uint32_t pa1 = f2tf32(odd ? q11 : q10);
            uint32_t pa2 = f2tf32(odd ? r01 : r00);
            uint32_t pa3 = f2tf32(odd ? r11 : r10);
            const int kb = kc * 8;
#pragma unroll
            for (int nd = 0; nd < 8; nd++) {
                uint32_t b0 = __float_as_uint(Vs[(kb + t) * KV_STR + nd * 8 + g]);
                uint32_t b1 = __float_as_uint(Vs[(kb + t + 4) * KV_STR + nd * 8 + g]);
                mma_tf32(ofrag[nd], pa0, pa1, pa2, pa3, b0, b1);
            }
        }
    }

    // ---- epilogue: write g_y pre-rounded to tf32 (gemm2's A operand) ----
    const float inv0 = 1.0f / l0, inv1 = 1.0f / l1;
    const int r0 = q0 + rowl, r1 = r0 + 8;
#pragma unroll
    for (int nd = 0; nd < 8; nd++) {
        const int c0 = nd * 8 + 2 * t;
        float2 v0 = make_float2(__uint_as_float(f2tf32(ofrag[nd][0] * inv0)),
                                __uint_as_float(f2tf32(ofrag[nd][1] * inv0)));
        float2 v1 = make_float2(__uint_as_float(f2tf32(ofrag[nd][2] * inv1)),
                                __uint_as_float(f2tf32(ofrag[nd][3] * inv1)));
        *(float2*)&g_y[((size_t)b * SS + r0) * EE + h * 64 + c0] = v0;
        *(float2*)&g_y[((size_t)b * SS + r1) * EE + h * 64 + c0] = v1;
    }
}

// ---------------------------------------------------------------------------
extern "C" void kernel_launch(void* const* d_in, const int* in_sizes, int n_in,
                              void* d_out, int out_size) {
    const float* x = nullptr;
    const float* W_attn = nullptr;
    const float* b_attn = nullptr;
    const float* W_proj = nullptr;
    const float* b_proj = nullptr;
    const int* att_mask = nullptr;
    for (int i = 0; i < n_in; i++) {
        switch (in_sizes[i]) {
            case BB * SS * EE:   x = (const float*)d_in[i]; break;
            case EE * 3 * EE:    W_attn = (const float*)d_in[i]; break;
            case 3 * EE:         b_attn = (const float*)d_in[i]; break;
            case EE * EE:        W_proj = (const float*)d_in[i]; break;
            case EE:             b_proj = (const float*)d_in[i]; break;
            case BB * SS:        att_mask = (const int*)d_in[i]; break;
            default: break;
        }
    }
    float* out = (float*)d_out;

    static bool attr_set = false;
    if (!attr_set) {
        cudaFuncSetAttribute(attn_mma, cudaFuncAttributeMaxDynamicSharedMemorySize,
                             ATTN_SMEM_BYTES);
        cudaFuncSetAttribute(gemm_mma<1>, cudaFuncAttributeMaxDynamicSharedMemorySize,
                             GEMM_SMEM);
        cudaFuncSetAttribute(gemm_mma<2>, cudaFuncAttributeMaxDynamicSharedMemorySize,
                             GEMM_SMEM);
        attr_set = true;
    }

    uint32_t *xt, *wat, *wpt;
    cudaGetSymbolAddress((void**)&xt, g_xt);
    cudaGetSymbolAddress((void**)&wat, g_wat);
    cudaGetSymbolAddress((void**)&wpt, g_wpt);

    // 0) Pre-convert inputs to tf32 bit arrays
    {
        int n4;
        n4 = BB * SS * EE / 4;
        cvt_tf32_kernel<<<(n4 + 255) / 256, 256>>>((const float4*)x, (uint4*)xt, n4);
        n4 = EE * 3 * EE / 4;
        cvt_tf32_kernel<<<(n4 + 255) / 256, 256>>>((const float4*)W_attn, (uint4*)wat, n4);
        n4 = EE * EE / 4;
        cvt_tf32_kernel<<<(n4 + 255) / 256, 256>>>((const float4*)W_proj, (uint4*)wpt, n4);
    }

    // 1) QKV GEMM (tf32 mma.sync) + tf32-rounded scatter
    gemm_mma<1><<<dim3(3 * EE / 128, BB * SS / 128), 256, GEMM_SMEM>>>(
        xt, wat, b_attn, nullptr, 3 * EE);

    // 2) Flash attention (tf32 mma.sync, Q fragments in registers)
    attn_mma<<<dim3(SS / 128, BB * HH), 256, ATTN_SMEM_BYTES>>>(att_mask);

    // 3) Projection GEMM (reads tf32-rounded g_y)
    gemm_mma<2><<<dim3(EE / 128, BB * SS / 128), 256, GEMM_SMEM>>>(
        nullptr, wpt, b_proj, out, EE);
}

// round 16
// speedup vs baseline: 2.4022x; 1.7353x over previous
#include <cuda_runtime.h>
#include <cuda_fp16.h>
#include <math.h>
#include <cstdint>

#define BB 4
#define SS 2048
#define EE 768
#define HH 12
#define DD 64
#define GK 768

// Scratch (static device globals: no allocation allowed). All fp16.
__device__ __half g_qh[(size_t)BB * HH * SS * DD];   // [bh][s][d]
__device__ __half g_kh[(size_t)BB * HH * SS * DD];   // [bh][s][d]
__device__ __half g_vth[(size_t)BB * HH * DD * SS];  // [bh][d][s]  (transposed!)
__device__ __half g_yh[(size_t)BB * SS * EE];        // [b*s][e]
__device__ __half g_xh[(size_t)BB * SS * EE];        // x -> fp16
__device__ __half g_wah[(size_t)3 * EE * EE];        // W_attn^T [N=2304][K=768] fp16
__device__ __half g_wph[(size_t)EE * EE];            // W_proj^T [N=768][K=768] fp16

// ======================= helpers ============================================
__device__ __forceinline__ uint32_t smem_u32(const void* p) {
    uint32_t a;
    asm("{ .reg .u64 t; cvta.to.shared.u64 t, %1; cvt.u32.u64 %0, t; }" : "=r"(a) : "l"(p));
    return a;
}
__device__ __forceinline__ void cp16(uint32_t dst, const void* src) {
    asm volatile("cp.async.cg.shared.global [%0], [%1], 16;" :: "r"(dst), "l"(src) : "memory");
}
__device__ __forceinline__ void cp_commit() {
    asm volatile("cp.async.commit_group;" ::: "memory");
}
template <int N>
__device__ __forceinline__ void cp_wait() {
    asm volatile("cp.async.wait_group %0;" :: "n"(N) : "memory");
}
// fp16 mma, fp32 accumulate (sm_80+, family-safe)
__device__ __forceinline__ void mma_h(float* d, uint32_t a0, uint32_t a1, uint32_t a2,
                                      uint32_t a3, uint32_t b0, uint32_t b1) {
    asm volatile(
        "mma.sync.aligned.m16n8k16.row.col.f32.f16.f16.f32 "
        "{%0,%1,%2,%3}, {%4,%5,%6,%7}, {%8,%9}, {%0,%1,%2,%3};"
        : "+f"(d[0]), "+f"(d[1]), "+f"(d[2]), "+f"(d[3])
        : "r"(a0), "r"(a1), "r"(a2), "r"(a3), "r"(b0), "r"(b1));
}
// pack two fp32 -> fp16x2 bits (lo = first arg)
__device__ __forceinline__ uint32_t packh2(float lo, float hi) {
    __half2 h = __floats2half2_rn(lo, hi);
    return *(uint32_t*)&h;
}

// Fast exp2 on FMA pipe
__device__ __forceinline__ float fexp2(float x) {
    x = fmaxf(x, -126.f);
    float z = x + 12582912.f;
    int n = __float_as_int(z) - 0x4B400000;
    float fi = z - 12582912.f;
    float f = x - fi;
    float r = 1.3333558146e-3f;
    r = fmaf(r, f, 9.6181291e-3f);
    r = fmaf(r, f, 5.5504108664e-2f);
    r = fmaf(r, f, 2.4022650695910e-1f);
    r = fmaf(r, f, 6.9314718055995e-1f);
    r = fmaf(r, f, 1.0f);
    return r * __int_as_float((n + 127) << 23);
}

// ======================= prepass: fp32 -> fp16 ==============================
__global__ void cvt_h4(const float4* __restrict__ src, uint2* __restrict__ dst, int n4) {
    int i = blockIdx.x * blockDim.x + threadIdx.x;
    if (i < n4) {
        float4 v = src[i];
        dst[i] = make_uint2(packh2(v.x, v.y), packh2(v.z, v.w));
    }
}
// W [K][N] fp32 -> Wt [N][K] fp16
__global__ void transpose_h(const float* __restrict__ W, __half* __restrict__ Wt,
                            int K, int N) {
    __shared__ float t[32][33];
    const int nb = blockIdx.x * 32, kb = blockIdx.y * 32;
    const int tx = threadIdx.x, ty = threadIdx.y;  // 32 x 8
#pragma unroll
    for (int i = 0; i < 32; i += 8) t[ty + i][tx] = W[(size_t)(kb + ty + i) * N + nb + tx];
    __syncthreads();
#pragma unroll
    for (int i = 0; i < 32; i += 8)
        Wt[(size_t)(nb + ty + i) * K + kb + tx] = __float2half(t[tx][ty + i]);
}

// ======================= fp16 mma.sync GEMM =================================
// C[M,N] = A[M,768] @ Wt^T + bias. 128x128 tile, BK=32, cp.async double buf.
// A/B smem rows: 32 halves + 8 pad = 40 halves (20 words) -> operand LDS
// banks 20g+t (+4): all-32-distinct, conflict-free.
// MODE 1: QKV scatter (Q/K fp16 [s][d]; V fp16 transposed [d][s]).
// MODE 2: A := g_yh, fp32 C output + bias.
#define ABUF_H 10240           // 128*40*2
#define STAGE_H (2 * ABUF_H)   // 20480
#define GEMM_SMEM_H (2 * STAGE_H)  // 40960 (static, <48KB)

template <int MODE>
__global__ __launch_bounds__(256) void gemm_h(const __half* __restrict__ A_,
                                              const __half* __restrict__ Wt,
                                              const float* __restrict__ bias,
                                              float* __restrict__ C, int N) {
    __shared__ char sm[GEMM_SMEM_H];
    const uint32_t sbase = smem_u32(sm);

    const __half* A = (MODE == 2) ? (const __half*)g_yh : A_;
    const int tid = threadIdx.x;
    const int wid = tid >> 5;
    const int lane = tid & 31;
    const int g = lane >> 2;
    const int t = lane & 3;
    const int bm = blockIdx.y * 128;
    const int bn = blockIdx.x * 128;
    const int wm = (wid >> 2) * 64;
    const int wn = (wid & 3) * 32;

    float acc[4][4][4];
#pragma unroll
    for (int mi = 0; mi < 4; mi++)
#pragma unroll
        for (int ni = 0; ni < 4; ni++)
#pragma unroll
            for (int r = 0; r < 4; r++) acc[mi][ni][r] = 0.f;

#define HISSUE(s, buf)                                                                   \
    {                                                                                    \
        const int k0_ = (s) * 32;                                                        \
        const uint32_t sa_ = sbase + (buf) * STAGE_H;                                    \
        const uint32_t sb_ = sa_ + ABUF_H;                                               \
        _Pragma("unroll") for (int it = 0; it < 2; ++it) {                               \
            const int c_ = tid + it * 256;                                               \
            const int row_ = c_ >> 2;                                                    \
            const int ch_ = c_ & 3;                                                      \
            cp16(sa_ + row_ * 80 + ch_ * 16,                                             \
                 A + (size_t)(bm + row_) * GK + k0_ + ch_ * 8);                          \
            cp16(sb_ + row_ * 80 + ch_ * 16,                                             \
                 Wt + (size_t)(bn + row_) * GK + k0_ + ch_ * 8);                         \
        }                                                                                \
        cp_commit();                                                                     \
    }

    HISSUE(0, 0);
    HISSUE(1, 1);

    for (int s = 0; s < 24; ++s) {
        const int buf = s & 1;
        if (s == 23) cp_wait<0>(); else cp_wait<1>();
        __syncthreads();

        const uint32_t* Aw = (const uint32_t*)(sm + buf * STAGE_H);
        const uint32_t* Bw = (const uint32_t*)(sm + buf * STAGE_H + ABUF_H);

#pragma unroll
        for (int kc = 0; kc < 2; ++kc) {
            const int kw = kc * 8 + t;
            uint32_t b0[4], b1[4];
#pragma unroll
            for (int ni = 0; ni < 4; ++ni) {
                const int n = wn + ni * 8 + g;
                b0[ni] = Bw[n * 20 + kw];
                b1[ni] = Bw[n * 20 + kw + 4];
            }
#pragma unroll
            for (int mi = 0; mi < 4; ++mi) {
                const int r = wm + mi * 16 + g;
                uint32_t a0 = Aw[r * 20 + kw];
                uint32_t a1 = Aw[(r + 8) * 20 + kw];
                uint32_t a2 = Aw[r * 20 + kw + 4];
                uint32_t a3 = Aw[(r + 8) * 20 + kw + 4];
#pragma unroll
                for (int ni = 0; ni < 4; ++ni)
                    mma_h(acc[mi][ni], a0, a1, a2, a3, b0[ni], b1[ni]);
            }
        }
        __syncthreads();
        if (s + 2 < 24) HISSUE(s + 2, buf);
    }

#pragma unroll
    for (int mi = 0; mi < 4; ++mi) {
#pragma unroll
        for (int ni = 0; ni < 4; ++ni) {
            const int r0 = bm + wm + mi * 16 + g;
            const int c0 = bn + wn + ni * 8 + 2 * t;
            const float bz0 = __ldg(&bias[c0]);
            const float bz1 = __ldg(&bias[c0 + 1]);
            const float v00 = acc[mi][ni][0] + bz0, v01 = acc[mi][ni][1] + bz1;
            const float v10 = acc[mi][ni][2] + bz0, v11 = acc[mi][ni][3] + bz1;
            if (MODE == 1) {
                const int sec = c0 / EE;
                const int e = c0 - sec * EE;
                const int h = e >> 6, d = e & 63;
                const int b0i = r0 >> 11, s0i = r0 & 2047;
                const int r1 = r0 + 8;
                const int b1i = r1 >> 11, s1i = r1 & 2047;
                if (sec < 2) {
                    __half* dst = (sec == 0) ? g_qh : g_kh;
                    *(uint32_t*)&dst[(((size_t)b0i * HH + h) * SS + s0i) * DD + d] =
                        packh2(v00, v01);
                    *(uint32_t*)&dst[(((size_t)b1i * HH + h) * SS + s1i) * DD + d] =
                        packh2(v10, v11);
                } else {
                    // V transposed: [bh][d][s]
                    __half* vt0 = g_vth + (((size_t)b0i * HH + h) * DD + d) * SS;
                    __half* vt1 = g_vth + (((size_t)b1i * HH + h) * DD + d) * SS;
                    vt0[s0i] = __float2half(v00);
                    vt0[SS + s0i] = __float2half(v01);
                    vt1[s1i] = __float2half(v10);
                    vt1[SS + s1i] = __float2half(v11);
                }
            } else {
                *(float2*)&C[(size_t)r0 * N + c0] = make_float2(v00, v01);
                *(float2*)&C[(size_t)(r0 + 8) * N + c0] = make_float2(v10, v11);
            }
        }
    }
}

// ======================= Flash attention via fp16 mma =======================
// q-tile 128, k-tile 64, 8 warps; warp w owns q rows [16w, 16w+16).
// Q frags in registers (fp16 pairs). K natural [key][d] (b-frag pairs
// contiguous); V pre-transposed [d][key]. Rows 72 halves (36 words):
// operand LDS banks 4g+t (+4) all-distinct. PV A-frags come straight from
// the score accumulator pairs -> no shuffles.
#define KVW 36  // words per smem row (72 halves)

__global__ __launch_bounds__(256, 2) void attn_h(const int* __restrict__ att_mask) {
    __shared__ __half KsS[64 * 72];
    __shared__ __half VtS[64 * 72];
    __shared__ int mskS[64];

    const int qt = (int)gridDim.x - 1 - (int)blockIdx.x;
    const int bh = blockIdx.y;
    const int b = bh / HH;
    const int h = bh % HH;
    const int tid = threadIdx.x;
    const int wid = tid >> 5;
    const int lane = tid & 31;
    const int g = lane >> 2;
    const int t = lane & 3;
    const int q0 = qt * 128;

    const __half* kptr = g_kh + (size_t)bh * SS * DD;
    const __half* vtp = g_vth + (size_t)bh * DD * SS;

    const int rowl = wid * 16 + g;
    const int qg0 = q0 + rowl, qg1 = qg0 + 8;
    const int ktmax = 2 * qt + 1;

    // Q fragments once from gmem (fp16 pairs, 16 regs)
    uint32_t qf[4][4];
    {
        const __half* qr0 = g_qh + (size_t)bh * SS * DD + (size_t)(q0 + rowl) * DD;
        const __half* qr1 = qr0 + 8 * DD;
#pragma unroll
        for (int dk = 0; dk < 4; dk++) {
            const int k0 = dk * 16 + 2 * t;
            qf[dk][0] = *(const uint32_t*)(qr0 + k0);
            qf[dk][1] = *(const uint32_t*)(qr1 + k0);
            qf[dk][2] = *(const uint32_t*)(qr0 + k0 + 8);
            qf[dk][3] = *(const uint32_t*)(qr1 + k0 + 8);
        }
    }

    float ofrag[8][4];
#pragma unroll
    for (int nd = 0; nd < 8; nd++)
#pragma unroll
        for (int r = 0; r < 4; r++) ofrag[nd][r] = 0.f;
    float m0 = -1e30f, m1 = -1e30f, l0 = 0.f, l1 = 0.f;

    const float SC = 0.125f * 1.4426950408889634f;

    for (int kt = 0; kt <= ktmax; kt++) {
        __syncthreads();
        // K tile [64 keys][64 d] + V tile [64 d][64 keys], 16B chunks
#pragma unroll
        for (int it = 0; it < 2; it++) {
            const int c = tid + it * 256;
            const int row = c >> 3;
            const int ch = c & 7;
            *(uint4*)((char*)KsS + row * 144 + ch * 16) =
                *(const uint4*)(kptr + (size_t)(kt * 64 + row) * DD + ch * 8);
            *(uint4*)((char*)VtS + row * 144 + ch * 16) =
                *(const uint4*)(vtp + (size_t)row * SS + kt * 64 + ch * 8);
        }
        if (tid < 64) mskS[tid] = att_mask[b * SS + kt * 64 + tid];
        __syncthreads();

        const uint32_t* Kw = (const uint32_t*)KsS;
        const uint32_t* Vw = (const uint32_t*)VtS;

        // ---- scores: 8 key-frags over D=64 (4 k16 chunks) ----
        float sf[8][4];
#pragma unroll
        for (int ni = 0; ni < 8; ni++)
#pragma unroll
            for (int r = 0; r < 4; r++) sf[ni][r] = 0.f;
#pragma unroll
        for (int dk = 0; dk < 4; dk++) {
            const int kw = dk * 8 + t;
#pragma unroll
            for (int ni = 0; ni < 8; ni++) {
                const uint32_t b0 = Kw[(ni * 8 + g) * KVW + kw];
                const uint32_t b1 = Kw[(ni * 8 + g) * KVW + kw + 4];
                mma_h(sf[ni], qf[dk][0], qf[dk][1], qf[dk][2], qf[dk][3], b0, b1);
            }
        }

        // ---- softmax (log2 domain) ----
        const bool tileFull = (kt * 64 + 63) <= q0;
        float mx0 = -1e30f, mx1 = -1e30f;
#pragma unroll
        for (int ni = 0; ni < 8; ni++) {
            const int cl0 = ni * 8 + 2 * t;
            const int cg0 = kt * 64 + cl0;
            const float tb0 = mskS[cl0] ? 0.f : -1e30f;
            const float tb1 = mskS[cl0 + 1] ? 0.f : -1e30f;
            float v00 = fmaf(sf[ni][0], SC, tb0);
            float v01 = fmaf(sf[ni][1], SC, tb1);
            float v10 = fmaf(sf[ni][2], SC, tb0);
            float v11 = fmaf(sf[ni][3], SC, tb1);
            if (!tileFull) {
                if (cg0 > qg0) v00 = -1e30f;
                if (cg0 + 1 > qg0) v01 = -1e30f;
                if (cg0 > qg1) v10 = -1e30f;
                if (cg0 + 1 > qg1) v11 = -1e30f;
            }
            sf[ni][0] = v00; sf[ni][1] = v01; sf[ni][2] = v10; sf[ni][3] = v11;
            mx0 = fmaxf(mx0, fmaxf(v00, v01));
            mx1 = fmaxf(mx1, fmaxf(v10, v11));
        }
        mx0 = fmaxf(mx0, __shfl_xor_sync(0xffffffffu, mx0, 1));
        mx0 = fmaxf(mx0, __shfl_xor_sync(0xffffffffu, mx0, 2));
        mx1 = fmaxf(mx1, __shfl_xor_sync(0xffffffffu, mx1, 1));
        mx1 = fmaxf(mx1, __shfl_xor_sync(0xffffffffu, mx1, 2));
        const float mn0 = fmaxf(m0, mx0), mn1 = fmaxf(m1, mx1);
        const float al0 = fexp2(m0 - mn0), al1 = fexp2(m1 - mn1);
        float s0 = 0.f, s1 = 0.f;
#pragma unroll
        for (int ni = 0; ni < 8; ni++) {
            sf[ni][0] = fexp2(sf[ni][0] - mn0);
            sf[ni][1] = fexp2(sf[ni][1] - mn0);
            sf[ni][2] = fexp2(sf[ni][2] - mn1);
            sf[ni][3] = fexp2(sf[ni][3] - mn1);
            s0 += sf[ni][0] + sf[ni][1];
            s1 += sf[ni][2] + sf[ni][3];
        }
        s0 += __shfl_xor_sync(0xffffffffu, s0, 1);
        s0 += __shfl_xor_sync(0xffffffffu, s0, 2);
        s1 += __shfl_xor_sync(0xffffffffu, s1, 1);
        s1 += __shfl_xor_sync(0xffffffffu, s1, 2);
        l0 = l0 * al0 + s0;
        l1 = l1 * al1 + s1;
        m0 = mn0;
        m1 = mn1;
#pragma unroll
        for (int nd = 0; nd < 8; nd++) {
            ofrag[nd][0] *= al0;
            ofrag[nd][1] *= al0;
            ofrag[nd][2] *= al1;
            ofrag[nd][3] *= al1;
        }

        // ---- PV: A-frags pack straight from accumulator pairs (no shuffles) ----
#pragma unroll
        for (int kc = 0; kc < 4; kc++) {
            const uint32_t pa0 = packh2(sf[2 * kc][0], sf[2 * kc][1]);
            const uint32_t pa1 = packh2(sf[2 * kc][2], sf[2 * kc][3]);
            const uint32_t pa2 = packh2(sf[2 * kc + 1][0], sf[2 * kc + 1][1]);
            const uint32_t pa3 = packh2(sf[2 * kc + 1][2], sf[2 * kc + 1][3]);
            const int kw = kc * 8 + t;
#pragma unroll
            for (int nd = 0; nd < 8; nd++) {
                const uint32_t b0 = Vw[(nd * 8 + g) * KVW + kw];
                const uint32_t b1 = Vw[(nd * 8 + g) * KVW + kw + 4];
                mma_h(ofrag[nd], pa0, pa1, pa2, pa3, b0, b1);
            }
        }
    }

    // ---- epilogue: write g_yh fp16 ----
    const float inv0 = 1.0f / l0, inv1 = 1.0f / l1;
    const int r0 = q0 + rowl, r1 = r0 + 8;
#pragma unroll
    for (int nd = 0; nd < 8; nd++) {
        const int c0 = nd * 8 + 2 * t;
        *(uint32_t*)&g_yh[((size_t)b * SS + r0) * EE + h * 64 + c0] =
            packh2(ofrag[nd][0] * inv0, ofrag[nd][1] * inv0);
        *(uint32_t*)&g_yh[((size_t)b * SS + r1) * EE + h * 64 + c0] =
            packh2(ofrag[nd][2] * inv1, ofrag[nd][3] * inv1);
    }
}

// ---------------------------------------------------------------------------
extern "C" void kernel_launch(void* const* d_in, const int* in_sizes, int n_in,
                              void* d_out, int out_size) {
    const float* x = nullptr;
    const float* W_attn = nullptr;
    const float* b_attn = nullptr;
    const float* W_proj = nullptr;
    const float* b_proj = nullptr;
    const int* att_mask = nullptr;
    for (int i = 0; i < n_in; i++) {
        switch (in_sizes[i]) {
            case BB * SS * EE:   x = (const float*)d_in[i]; break;
            case EE * 3 * EE:    W_attn = (const float*)d_in[i]; break;
            case 3 * EE:         b_attn = (const float*)d_in[i]; break;
            case EE * EE:        W_proj = (const float*)d_in[i]; break;
            case EE:             b_proj = (const float*)d_in[i]; break;
            case BB * SS:        att_mask = (const int*)d_in[i]; break;
            default: break;
        }
    }
    float* out = (float*)d_out;

    __half *xh, *wah, *wph;
    cudaGetSymbolAddress((void**)&xh, g_xh);
    cudaGetSymbolAddress((void**)&wah, g_wah);
    cudaGetSymbolAddress((void**)&wph, g_wph);

    // 0) Prepass: x -> fp16; W -> transposed fp16 [N][K]
    {
        const int n4 = BB * SS * EE / 4;
        cvt_h4<<<(n4 + 255) / 256, 256>>>((const float4*)x, (uint2*)xh, n4);
        transpose_h<<<dim3(3 * EE / 32, EE / 32), dim3(32, 8)>>>(W_attn, wah, EE, 3 * EE);
        transpose_h<<<dim3(EE / 32, EE / 32), dim3(32, 8)>>>(W_proj, wph, EE, EE);
    }

    // 1) QKV GEMM (fp16 mma) + scatter: Q/K [s][d], V transposed [d][s]
    gemm_h<1><<<dim3(3 * EE / 128, BB * SS / 128), 256>>>(xh, wah, b_attn, nullptr,
                                                          3 * EE);

    // 2) Flash attention (fp16 mma, shuffle-free PV)
    attn_h<<<dim3(SS / 128, BB * HH), 256>>>(att_mask);

    // 3) Projection GEMM (reads g_yh fp16, fp32 output)
    gemm_h<2><<<dim3(EE / 128, BB * SS / 128), 256>>>(nullptr, wph, b_proj, out, EE);
}